// round 3
// baseline (speedup 1.0000x reference)
#include <cuda_runtime.h>
#include <cstdint>
#include <cstddef>

// ---------------------------------------------------------------------------
// VQ quantizer:  z (NT x 64) vs codebook (K x 64)
// outputs (concat float32): e[NT], z_q[NT*64], sim[NT*K], loss[NT]
// ---------------------------------------------------------------------------

#define D        64
#define DP       68     // padded smem row (floats): conflict-free by construction
#define BM       64     // tokens per block
#define BN       128    // codes per chunk
#define THREADS  256
#define TT       8      // tokens per thread
#define TC       4      // codes per lane  (code = lane + 32*i)

#define FMA2(c, a, b) \
    asm("fma.rn.f32x2 %0, %1, %2, %3;" : "=l"(c) : "l"(a), "l"(b), "l"(c))

#define CP_ASYNC16(dst, src) \
    asm volatile("cp.async.ca.shared.global [%0], [%1], 16;" :: "r"(dst), "l"(src))
#define CP_COMMIT()  asm volatile("cp.async.commit_group;")
#define CP_WAIT(n)   asm volatile("cp.async.wait_group %0;" :: "n"(n))

__device__ __forceinline__ unsigned long long pack2(float x, float y) {
    unsigned long long r;
    asm("mov.b64 %0, {%1, %2};" : "=l"(r) : "f"(x), "f"(y));
    return r;
}
__device__ __forceinline__ float2 unpack2(unsigned long long v) {
    float2 r;
    asm("mov.b64 {%0, %1}, %2;" : "=f"(r.x), "=f"(r.y) : "l"(v));
    return r;
}

// codebook norms (precomputed; K <= 4096)
__device__ float g_en2[4096];
__device__ float g_einv[4096];

__global__ void vq_enorm_kernel(const float* __restrict__ cbk, int K) {
    int k = blockIdx.x * blockDim.x + threadIdx.x;
    if (k >= K) return;
    const float4* row = reinterpret_cast<const float4*>(cbk + (size_t)k * D);
    float s = 0.f;
#pragma unroll
    for (int i = 0; i < D / 4; ++i) {
        float4 v = row[i];
        s += v.x * v.x + v.y * v.y + v.z * v.z + v.w * v.w;
    }
    g_en2[k]  = s;
    g_einv[k] = rsqrtf(s);
}

// dynamic smem (floats):
//   zs   : BM*DP              (17408 B)
//   es0  : BN*DP              (34816 B)   codebook chunk, double-buffered
//   es1  : BN*DP              (34816 B)
//   znorm: BM, zinv: BM       (512 B)
__global__ void __launch_bounds__(THREADS, 2)
vq_main_kernel(const float* __restrict__ z,
               const float* __restrict__ cbk,
               int K,
               float* __restrict__ e_out,
               float* __restrict__ zq_out,
               float* __restrict__ sim_out,
               float* __restrict__ loss_out) {
    extern __shared__ float smem[];
    float* zs     = smem;                         // [BM][DP]
    float* es0    = zs + BM * DP;                 // [BN][DP]
    float* es1    = es0 + BN * DP;                // [BN][DP]
    float* znorms = es1 + BN * DP;
    float* zinvs  = znorms + BM;

    const int tid  = threadIdx.x;
    const int lane = tid & 31;
    const int warp = tid >> 5;
    const int t0   = warp * TT;

    unsigned smem_base;
    asm("{ .reg .u64 t; cvta.to.shared.u64 t, %1; cvt.u32.u64 %0, t; }"
        : "=r"(smem_base) : "l"((void*)smem));
    const unsigned zs_s  = smem_base;
    const unsigned es_s0 = smem_base + BM * DP * 4;
    const unsigned es_s1 = es_s0 + BN * DP * 4;

    const int nchunks = K / BN;

    // ---- prologue: group0 = z tile + chunk0, group1 = chunk1 ----------
    {
        const float* zg = z + (size_t)blockIdx.x * BM * D;
#pragma unroll
        for (int idx = tid; idx < BM * (D / 4); idx += THREADS) {
            int q = idx & 15, r = idx >> 4;
            CP_ASYNC16(zs_s + (r * DP + 4 * q) * 4, zg + r * D + 4 * q);
        }
#pragma unroll
        for (int idx = tid; idx < BN * (D / 4); idx += THREADS) {
            int q = idx & 15, c = idx >> 4;
            CP_ASYNC16(es_s0 + (c * DP + 4 * q) * 4, cbk + (size_t)c * D + 4 * q);
        }
        CP_COMMIT();
#pragma unroll
        for (int idx = tid; idx < BN * (D / 4); idx += THREADS) {
            int q = idx & 15, c = idx >> 4;
            CP_ASYNC16(es_s1 + (c * DP + 4 * q) * 4, cbk + (size_t)(BN + c) * D + 4 * q);
        }
        CP_COMMIT();
    }
    CP_WAIT(1);            // z tile + chunk0 resident; chunk1 still in flight
    __syncthreads();

    // ---- per-token norms ----------------------------------------------
    if (tid < BM) {
        float s = 0.f;
#pragma unroll
        for (int i = 0; i < D / 4; ++i) {
            float4 v = *reinterpret_cast<const float4*>(zs + tid * DP + 4 * i);
            s += v.x * v.x + v.y * v.y + v.z * v.z + v.w * v.w;
        }
        znorms[tid] = s;
        zinvs[tid]  = rsqrtf(s);
    }
    __syncthreads();

    float mind[TT];
    int   mini[TT];
#pragma unroll
    for (int t = 0; t < TT; ++t) { mind[t] = 3.4e38f; mini[t] = 0; }

    for (int cbi = 0; cbi < nchunks; ++cbi) {
        const float* es = (cbi & 1) ? es1 : es0;

        // epilogue constants — issued now, consumed after compute (hidden)
        float en2r[TC], einvr[TC];
#pragma unroll
        for (int i = 0; i < TC; ++i) {
            en2r[i]  = __ldg(&g_en2[cbi * BN + lane + 32 * i]);
            einvr[i] = __ldg(&g_einv[cbi * BN + lane + 32 * i]);
        }

        // ---- main micro-kernel: 8 tokens x 4 codes per lane ----------
        unsigned long long acc[TT][TC];
#pragma unroll
        for (int t = 0; t < TT; ++t)
#pragma unroll
            for (int i = 0; i < TC; ++i) acc[t][i] = 0ull;

#pragma unroll 4
        for (int q = 0; q < D / 4; ++q) {
            unsigned long long blo[TC], bhi[TC];
#pragma unroll
            for (int i = 0; i < TC; ++i) {
                float4 b4 = *reinterpret_cast<const float4*>(es + (lane + 32 * i) * DP + 4 * q);
                blo[i] = pack2(b4.x, b4.y);
                bhi[i] = pack2(b4.z, b4.w);
            }
#pragma unroll
            for (int t = 0; t < TT; ++t) {
                float4 a4 = *reinterpret_cast<const float4*>(zs + (t0 + t) * DP + 4 * q); // broadcast
                unsigned long long alo = pack2(a4.x, a4.y);
                unsigned long long ahi = pack2(a4.z, a4.w);
#pragma unroll
                for (int i = 0; i < TC; ++i) {
                    FMA2(acc[t][i], alo, blo[i]);
                    FMA2(acc[t][i], ahi, bhi[i]);
                }
            }
        }

        // ---- epilogue: dist/argmin + fused coalesced sim writes ------
#pragma unroll
        for (int t = 0; t < TT; ++t) {
            float nzv = znorms[t0 + t];
            float ziv = zinvs[t0 + t];
            size_t row = ((size_t)blockIdx.x * BM + t0 + t) * (size_t)K + cbi * BN;
#pragma unroll
            for (int i = 0; i < TC; ++i) {
                int   cl  = lane + 32 * i;
                float2 p  = unpack2(acc[t][i]);
                float dot = p.x + p.y;
                float dist = nzv - 2.f * dot + en2r[i];
                int   gc   = cbi * BN + cl;
                if (dist < mind[t] || (dist == mind[t] && gc < mini[t])) {
                    mind[t] = dist; mini[t] = gc;
                }
                __stcs(sim_out + row + cl, dot * ziv * einvr[i]);   // 128B coalesced
            }
        }

        __syncthreads();   // all warps done reading this buffer

        if (cbi + 2 < nchunks) {
            // prefetch chunk cbi+2 into the buffer just freed
            const unsigned dst = (cbi & 1) ? es_s1 : es_s0;
            const float* base = cbk + (size_t)(cbi + 2) * BN * D;
#pragma unroll
            for (int idx = tid; idx < BN * (D / 4); idx += THREADS) {
                int q = idx & 15, c = idx >> 4;
                CP_ASYNC16(dst + (c * DP + 4 * q) * 4, base + (size_t)c * D + 4 * q);
            }
            CP_COMMIT();
            CP_WAIT(1);    // chunk cbi+1 resident; cbi+2 in flight
        } else {
            CP_WAIT(0);    // tail: ensure last chunk resident
        }
        __syncthreads();
    }

    // ---- final: argmin across the warp, zq gather, loss ---------------
#pragma unroll
    for (int t = 0; t < TT; ++t) {
        float d  = mind[t];
        int   ix = mini[t];
#pragma unroll
        for (int off = 16; off; off >>= 1) {
            float od = __shfl_xor_sync(0xffffffffu, d, off);
            int   oi = __shfl_xor_sync(0xffffffffu, ix, off);
            if (od < d || (od == d && oi < ix)) { d = od; ix = oi; }
        }
        int    tl  = t0 + t;
        size_t tok = (size_t)blockIdx.x * BM + tl;

        float2 ev = reinterpret_cast<const float2*>(cbk + (size_t)ix * D)[lane];
        reinterpret_cast<float2*>(zq_out + tok * D)[lane] = ev;

        float zx = zs[tl * DP + 2 * lane], zy = zs[tl * DP + 2 * lane + 1];
        float dx = zx - ev.x, dy = zy - ev.y;
        float s = dx * dx + dy * dy;
#pragma unroll
        for (int off = 16; off; off >>= 1) s += __shfl_xor_sync(0xffffffffu, s, off);

        if (lane == 0) {
            loss_out[tok] = 1.25f * sqrtf(s);
            e_out[tok]    = (float)ix;
        }
    }
}

extern "C" void kernel_launch(void* const* d_in, const int* in_sizes, int n_in,
                              void* d_out, int out_size) {
    const float* z   = (const float*)d_in[0];
    const float* cbk = (const float*)d_in[1];
    const int NT = in_sizes[0] / D;
    const int K  = in_sizes[1] / D;

    float* out      = (float*)d_out;
    float* e_out    = out;
    float* zq_out   = e_out + NT;
    float* sim_out  = zq_out + (size_t)NT * D;
    float* loss_out = sim_out + (size_t)NT * K;

    vq_enorm_kernel<<<(K + 255) / 256, 256>>>(cbk, K);

    const size_t smem = (size_t)(BM * DP + 2 * BN * DP + BM + BM) * 4;
    cudaFuncSetAttribute(vq_main_kernel, cudaFuncAttributeMaxDynamicSharedMemorySize, (int)smem);
    vq_main_kernel<<<NT / BM, THREADS, smem>>>(z, cbk, K, e_out, zq_out, sim_out, loss_out);
}

// round 4
// speedup vs baseline: 1.1447x; 1.1447x over previous
#include <cuda_runtime.h>
#include <cstdint>
#include <cstddef>

// ---------------------------------------------------------------------------
// VQ quantizer:  z (NT x 64) vs codebook (K x 64)
// outputs (concat float32): e[NT], z_q[NT*64], sim[NT*K], loss[NT]
// ---------------------------------------------------------------------------

#define D        64
#define DP       68     // padded smem row (floats): conflict-free by construction
#define BM       64     // tokens per block
#define BN       128    // codes per chunk
#define THREADS  256
#define TT       8      // tokens per thread
#define TC       4      // codes per lane  (code = lane + 32*i)

#define FMA2(c, a, b) \
    asm("fma.rn.f32x2 %0, %1, %2, %3;" : "=l"(c) : "l"(a), "l"(b), "l"(c))

// direct 16B shared load into two 64-bit regs (no pack MOVs)
#define LDS_V2U64(lo, hi, addr) \
    asm volatile("ld.shared.v2.b64 {%0, %1}, [%2];" : "=l"(lo), "=l"(hi) : "r"(addr))

#define CP_ASYNC16(dst, src) \
    asm volatile("cp.async.ca.shared.global [%0], [%1], 16;" :: "r"(dst), "l"(src))
#define CP_COMMIT()  asm volatile("cp.async.commit_group;")
#define CP_WAIT(n)   asm volatile("cp.async.wait_group %0;" :: "n"(n))

__device__ __forceinline__ float2 unpack2(unsigned long long v) {
    float2 r;
    asm("mov.b64 {%0, %1}, %2;" : "=f"(r.x), "=f"(r.y) : "l"(v));
    return r;
}

// codebook norms (precomputed; K <= 4096)
__device__ float g_en2[4096];
__device__ float g_einv[4096];

__global__ void vq_enorm_kernel(const float* __restrict__ cbk, int K) {
    int k = blockIdx.x * blockDim.x + threadIdx.x;
    if (k >= K) return;
    const float4* row = reinterpret_cast<const float4*>(cbk + (size_t)k * D);
    float s = 0.f;
#pragma unroll
    for (int i = 0; i < D / 4; ++i) {
        float4 v = row[i];
        s += v.x * v.x + v.y * v.y + v.z * v.z + v.w * v.w;
    }
    g_en2[k]  = s;
    g_einv[k] = rsqrtf(s);
}

// dynamic smem (floats):
//   zs   : BM*DP        (17408 B)
//   es0  : BN*DP        (34816 B)   codebook chunk, double-buffered
//   es1  : BN*DP        (34816 B)
//   en2s : K, einvs : K (8192 B for K=1024)   all-chunk norms, loaded once
//   znorm: BM, zinv: BM (512 B)
__global__ void __launch_bounds__(THREADS, 2)
vq_main_kernel(const float* __restrict__ z,
               const float* __restrict__ cbk,
               int K,
               float* __restrict__ e_out,
               float* __restrict__ zq_out,
               float* __restrict__ sim_out,
               float* __restrict__ loss_out) {
    extern __shared__ float smem[];
    float* zs     = smem;                         // [BM][DP]
    float* es0    = zs + BM * DP;                 // [BN][DP]
    float* es1    = es0 + BN * DP;                // [BN][DP]
    float* en2s   = es1 + BN * DP;                // [K]
    float* einvs  = en2s + K;                     // [K]
    float* znorms = einvs + K;                    // [BM]
    float* zinvs  = znorms + BM;                  // [BM]

    const int tid  = threadIdx.x;
    const int lane = tid & 31;
    const int warp = tid >> 5;
    const int t0   = warp * TT;

    unsigned smem_base;
    asm("{ .reg .u64 t; cvta.to.shared.u64 t, %1; cvt.u32.u64 %0, t; }"
        : "=r"(smem_base) : "l"((void*)smem));
    const unsigned zs_s  = smem_base;
    const unsigned es_sb[2] = { smem_base + BM * DP * 4u,
                                smem_base + (BM * DP + BN * DP) * 4u };

    const int nchunks = K / BN;

    // ---- prologue: async z tile + chunk0; plain LDG->STS for norms ----
    {
        const float* zg = z + (size_t)blockIdx.x * BM * D;
#pragma unroll
        for (int idx = tid; idx < BM * (D / 4); idx += THREADS) {
            int q = idx & 15, r = idx >> 4;
            CP_ASYNC16(zs_s + (r * DP + 4 * q) * 4, zg + r * D + 4 * q);
        }
#pragma unroll
        for (int idx = tid; idx < BN * (D / 4); idx += THREADS) {
            int q = idx & 15, c = idx >> 4;
            CP_ASYNC16(es_sb[0] + (c * DP + 4 * q) * 4, cbk + (size_t)c * D + 4 * q);
        }
        CP_COMMIT();
        for (int k = tid; k < K; k += THREADS) {
            en2s[k]  = g_en2[k];
            einvs[k] = g_einv[k];
        }
    }
    CP_WAIT(0);
    __syncthreads();

    // ---- per-token norms ----------------------------------------------
    if (tid < BM) {
        float s = 0.f;
#pragma unroll
        for (int i = 0; i < D / 4; ++i) {
            float4 v = *reinterpret_cast<const float4*>(zs + tid * DP + 4 * i);
            s += v.x * v.x + v.y * v.y + v.z * v.z + v.w * v.w;
        }
        znorms[tid] = s;
        zinvs[tid]  = rsqrtf(s);
    }
    __syncthreads();

    float mind[TT];
    int   mini[TT];
#pragma unroll
    for (int t = 0; t < TT; ++t) { mind[t] = 3.4e38f; mini[t] = 0; }

    // loop-invariant smem addresses
    unsigned za[TT];
#pragma unroll
    for (int t = 0; t < TT; ++t) za[t] = zs_s + (t0 + t) * DP * 4u;

    for (int cbi = 0; cbi < nchunks; ++cbi) {
        const int cur = cbi & 1;

        // ---- issue prefetch of NEXT chunk before computing this one ----
        if (cbi + 1 < nchunks) {
            const unsigned dst = es_sb[cur ^ 1];
            const float* base = cbk + (size_t)(cbi + 1) * BN * D;
#pragma unroll
            for (int idx = tid; idx < BN * (D / 4); idx += THREADS) {
                int q = idx & 15, c = idx >> 4;
                CP_ASYNC16(dst + (c * DP + 4 * q) * 4, base + (size_t)c * D + 4 * q);
            }
            CP_COMMIT();
        }

        // ---- main micro-kernel: 8 tokens x 4 codes per lane ------------
        unsigned ea[TC];
#pragma unroll
        for (int i = 0; i < TC; ++i) ea[i] = es_sb[cur] + (lane + 32 * i) * DP * 4u;

        unsigned long long acc[TT][TC];
#pragma unroll
        for (int t = 0; t < TT; ++t)
#pragma unroll
            for (int i = 0; i < TC; ++i) acc[t][i] = 0ull;

#pragma unroll
        for (int q = 0; q < D / 4; ++q) {
            unsigned long long blo[TC], bhi[TC];
#pragma unroll
            for (int i = 0; i < TC; ++i) LDS_V2U64(blo[i], bhi[i], ea[i] + 16u * q);
#pragma unroll
            for (int t = 0; t < TT; ++t) {
                unsigned long long alo, ahi;
                LDS_V2U64(alo, ahi, za[t] + 16u * q);    // warp-uniform broadcast
#pragma unroll
                for (int i = 0; i < TC; ++i) {
                    FMA2(acc[t][i], alo, blo[i]);
                    FMA2(acc[t][i], ahi, bhi[i]);
                }
            }
        }

        // ---- epilogue: dist/argmin + fused coalesced sim writes --------
#pragma unroll
        for (int t = 0; t < TT; ++t) {
            float nzv = znorms[t0 + t];
            float ziv = zinvs[t0 + t];
            size_t row = ((size_t)blockIdx.x * BM + t0 + t) * (size_t)K + cbi * BN;
#pragma unroll
            for (int i = 0; i < TC; ++i) {
                int   cl  = lane + 32 * i;
                int   gc  = cbi * BN + cl;
                float2 p  = unpack2(acc[t][i]);
                float dot = p.x + p.y;
                float dist = nzv - 2.f * dot + en2s[gc];
                if (dist < mind[t] || (dist == mind[t] && gc < mini[t])) {
                    mind[t] = dist; mini[t] = gc;
                }
                __stcs(sim_out + row + cl, dot * ziv * einvs[gc]);   // 128B coalesced
            }
        }

        // next buffer resident (long since landed) + all warps done with cur
        if (cbi + 1 < nchunks) CP_WAIT(0);
        __syncthreads();
    }

    // ---- final: argmin across the warp, zq gather, loss ---------------
#pragma unroll
    for (int t = 0; t < TT; ++t) {
        float d  = mind[t];
        int   ix = mini[t];
#pragma unroll
        for (int off = 16; off; off >>= 1) {
            float od = __shfl_xor_sync(0xffffffffu, d, off);
            int   oi = __shfl_xor_sync(0xffffffffu, ix, off);
            if (od < d || (od == d && oi < ix)) { d = od; ix = oi; }
        }
        int    tl  = t0 + t;
        size_t tok = (size_t)blockIdx.x * BM + tl;

        float2 ev = reinterpret_cast<const float2*>(cbk + (size_t)ix * D)[lane];
        reinterpret_cast<float2*>(zq_out + tok * D)[lane] = ev;

        float zx = zs[tl * DP + 2 * lane], zy = zs[tl * DP + 2 * lane + 1];
        float dx = zx - ev.x, dy = zy - ev.y;
        float s = dx * dx + dy * dy;
#pragma unroll
        for (int off = 16; off; off >>= 1) s += __shfl_xor_sync(0xffffffffu, s, off);

        if (lane == 0) {
            loss_out[tok] = 1.25f * sqrtf(s);
            e_out[tok]    = (float)ix;
        }
    }
}

extern "C" void kernel_launch(void* const* d_in, const int* in_sizes, int n_in,
                              void* d_out, int out_size) {
    const float* z   = (const float*)d_in[0];
    const float* cbk = (const float*)d_in[1];
    const int NT = in_sizes[0] / D;
    const int K  = in_sizes[1] / D;

    float* out      = (float*)d_out;
    float* e_out    = out;
    float* zq_out   = e_out + NT;
    float* sim_out  = zq_out + (size_t)NT * D;
    float* loss_out = sim_out + (size_t)NT * K;

    vq_enorm_kernel<<<(K + 255) / 256, 256>>>(cbk, K);

    const size_t smem = (size_t)(BM * DP + 2 * BN * DP + 2 * K + 2 * BM) * 4;
    cudaFuncSetAttribute(vq_main_kernel, cudaFuncAttributeMaxDynamicSharedMemorySize, (int)smem);
    vq_main_kernel<<<NT / BM, THREADS, smem>>>(z, cbk, K, e_out, zq_out, sim_out, loss_out);
}

// round 6
// speedup vs baseline: 1.3362x; 1.1673x over previous
#include <cuda_runtime.h>
#include <cuda_bf16.h>
#include <cstdint>
#include <cstddef>

// ---------------------------------------------------------------------------
// VQ quantizer via mma.sync (HMMA) bf16 triple-split GEMM (fp32-accurate dot).
//   z (NT x 64) vs codebook (1024 x 64)
//   outputs (concat f32): e[NT], z_q[NT*64], sim[NT*K], loss[NT]
// ---------------------------------------------------------------------------

#define D        64
#define BM       128                 // tokens per CTA
#define BN       128                 // codes per chunk
#define KTOT     1024
#define NCHUNK   (KTOT / BN)
#define THREADS  256

#define ROWB     144u                // padded row: 64 bf16 (128B) + 16B pad
#define SPLIT_B  (128u * ROWB)       // 18432 B per split tile
#define CHUNK_B  (3u * SPLIT_B)      // 55296 B per chunk (3 splits)

#define OFF_A    0u                  // A splits: 3 x 18432
#define OFF_B0   55296u              // B buffer 0
#define OFF_B1   110592u             // B buffer 1
#define OFF_EN2  165888u             // 4096 B
#define OFF_EINV 169984u             // 4096 B
#define OFF_ZN   174080u             // 512 B
#define OFF_ZI   174592u             // 512 B
#define OFF_MIN  175104u             // 512 B (winning index per row)
#define SMEM_REQ 175616u

#define CP_ASYNC16(dst, src) \
    asm volatile("cp.async.ca.shared.global [%0], [%1], 16;" :: "r"(dst), "l"(src))
#define CP_COMMIT()  asm volatile("cp.async.commit_group;")
#define CP_WAIT(n)   asm volatile("cp.async.wait_group %0;" :: "n"(n))

__device__ __forceinline__ uint32_t lds32(unsigned a) {
    uint32_t v;
    asm volatile("ld.shared.b32 %0, [%1];" : "=r"(v) : "r"(a));
    return v;
}

__device__ __forceinline__ void mma16816(float* d, const uint32_t* a, const uint32_t* b) {
    asm volatile(
        "mma.sync.aligned.m16n8k16.row.col.f32.bf16.bf16.f32 "
        "{%0,%1,%2,%3}, {%4,%5,%6,%7}, {%8,%9}, {%0,%1,%2,%3};"
        : "+f"(d[0]), "+f"(d[1]), "+f"(d[2]), "+f"(d[3])
        : "r"(a[0]), "r"(a[1]), "r"(a[2]), "r"(a[3]), "r"(b[0]), "r"(b[1]));
}

// ---------------- prep: codebook norms + padded bf16 split images -----------
// layout: [chunk][split][row 0..127][dim 0..71(pad)]  (pad stays zero)
__device__ unsigned short g_bsplit[NCHUNK * 3 * 128 * 72];
__device__ float g_en2[KTOT];
__device__ float g_einv[KTOT];

__global__ void vq_prep_norm(const float* __restrict__ cbk) {
    int k = blockIdx.x * blockDim.x + threadIdx.x;
    if (k >= KTOT) return;
    const float4* row = reinterpret_cast<const float4*>(cbk + (size_t)k * D);
    float s = 0.f;
#pragma unroll
    for (int i = 0; i < D / 4; ++i) {
        float4 v = row[i];
        s += v.x * v.x + v.y * v.y + v.z * v.z + v.w * v.w;
    }
    g_en2[k]  = s;
    g_einv[k] = rsqrtf(s);
}

__global__ void vq_prep_split(const float* __restrict__ cbk) {
    int idx = blockIdx.x * blockDim.x + threadIdx.x;   // 0 .. KTOT*D-1
    if (idx >= KTOT * D) return;
    int code = idx >> 6, d = idx & 63;
    int c = code >> 7, r = code & 127;
    float x = cbk[idx];
    __nv_bfloat16 b0 = __float2bfloat16(x);
    float r1 = x - __bfloat162float(b0);
    __nv_bfloat16 b1 = __float2bfloat16(r1);
    float r2 = r1 - __bfloat162float(b1);
    __nv_bfloat16 b2 = __float2bfloat16(r2);
    unsigned basei = (unsigned)(c * 3) * 9216u + (unsigned)r * 72u + (unsigned)d;
    g_bsplit[basei]          = __bfloat16_as_ushort(b0);
    g_bsplit[basei + 9216u]  = __bfloat16_as_ushort(b1);
    g_bsplit[basei + 18432u] = __bfloat16_as_ushort(b2);
}

// ---------------- main kernel ------------------------------------------------
__global__ void __launch_bounds__(THREADS, 1)
vq_mma_kernel(const float* __restrict__ z,
              const float* __restrict__ cbk,
              float* __restrict__ e_out,
              float* __restrict__ zq_out,
              float* __restrict__ sim_out,
              float* __restrict__ loss_out) {
    extern __shared__ unsigned char smp[];
    unsigned base;
    asm("{ .reg .u64 t; cvta.to.shared.u64 t, %1; cvt.u32.u64 %0, t; }"
        : "=r"(base) : "l"((void*)smp));

    const int tid   = threadIdx.x;
    const int warp  = tid >> 5;
    const int lane  = tid & 31;
    const int quad  = lane >> 2;     // 0..7
    const int qlane = lane & 3;      // 0..3

    float* en2s   = (float*)(smp + OFF_EN2);
    float* einvs  = (float*)(smp + OFF_EINV);
    float* znorms = (float*)(smp + OFF_ZN);
    float* zinvs  = (float*)(smp + OFF_ZI);
    int*   winidx = (int*)(smp + OFF_MIN);

    // ---- prefetch B chunks 0 and 1 -------------------------------------
    {
        const char* gb = (const char*)g_bsplit;
        for (unsigned i = tid * 16u; i < CHUNK_B; i += THREADS * 16u)
            CP_ASYNC16(base + OFF_B0 + i, gb + i);
        CP_COMMIT();
        for (unsigned i = tid * 16u; i < CHUNK_B; i += THREADS * 16u)
            CP_ASYNC16(base + OFF_B1 + i, gb + CHUNK_B + i);
        CP_COMMIT();
    }

    // ---- norms of codebook into smem -----------------------------------
    for (int k = tid; k < KTOT; k += THREADS) {
        en2s[k]  = g_en2[k];
        einvs[k] = g_einv[k];
    }

    // ---- build A split tiles (thread t<128 owns token-row t) -----------
    if (tid < BM) {
        const size_t tok = (size_t)blockIdx.x * BM + tid;
        const float4* zr = reinterpret_cast<const float4*>(z + tok * D);
        float zn = 0.f;
#pragma unroll
        for (int q = 0; q < 16; ++q) {
            float4 v = zr[q];
            zn += v.x * v.x + v.y * v.y + v.z * v.z + v.w * v.w;
            float xs[4] = {v.x, v.y, v.z, v.w};
            unsigned long long p0 = 0, p1 = 0, p2 = 0;
#pragma unroll
            for (int j = 0; j < 4; ++j) {
                float x = xs[j];
                __nv_bfloat16 b0 = __float2bfloat16(x);
                float rr1 = x - __bfloat162float(b0);
                __nv_bfloat16 b1 = __float2bfloat16(rr1);
                float rr2 = rr1 - __bfloat162float(b1);
                __nv_bfloat16 b2 = __float2bfloat16(rr2);
                p0 |= (unsigned long long)__bfloat16_as_ushort(b0) << (16 * j);
                p1 |= (unsigned long long)__bfloat16_as_ushort(b1) << (16 * j);
                p2 |= (unsigned long long)__bfloat16_as_ushort(b2) << (16 * j);
            }
            unsigned off = (unsigned)tid * ROWB + (unsigned)q * 8u;
            *(unsigned long long*)(smp + OFF_A + 0 * SPLIT_B + off) = p0;
            *(unsigned long long*)(smp + OFF_A + 1 * SPLIT_B + off) = p1;
            *(unsigned long long*)(smp + OFF_A + 2 * SPLIT_B + off) = p2;
        }
        znorms[tid] = zn;
        zinvs[tid]  = rsqrtf(zn);
    }

    CP_WAIT(1);                // chunk0 resident (chunk1 still in flight)
    __syncthreads();

    const int r0 = warp * 16 + quad;       // this thread's token rows
    const int r1 = r0 + 8;
    const float zn0 = znorms[r0], zn1 = znorms[r1];
    const float zi0 = zinvs[r0],  zi1 = zinvs[r1];
    const size_t rg0 = (size_t)blockIdx.x * BM + r0;
    const size_t rg1 = rg0 + 8;
    float* sim0 = sim_out + rg0 * (size_t)KTOT;
    float* sim1 = sim_out + rg1 * (size_t)KTOT;

    float mind0 = 3.4e38f, mind1 = 3.4e38f;
    int   mini0 = 0,       mini1 = 0;

    const unsigned aAbase = base + OFF_A + (unsigned)(warp * 16 + quad) * ROWB + (unsigned)qlane * 4u;

#pragma unroll 1
    for (int c = 0; c < NCHUNK; ++c) {
        const unsigned Bb = base + ((c & 1) ? OFF_B1 : OFF_B0)
                          + (unsigned)quad * ROWB + (unsigned)qlane * 4u;

        float acc[16][4];
#pragma unroll
        for (int nt = 0; nt < 16; ++nt)
#pragma unroll
            for (int j = 0; j < 4; ++j) acc[nt][j] = 0.f;

#pragma unroll
        for (int kk = 0; kk < 4; ++kk) {
            uint32_t A[3][4];
#pragma unroll
            for (int s = 0; s < 3; ++s) {
                unsigned a = aAbase + (unsigned)s * SPLIT_B + (unsigned)kk * 32u;
                A[s][0] = lds32(a);
                A[s][1] = lds32(a + 8u * ROWB);
                A[s][2] = lds32(a + 16u);
                A[s][3] = lds32(a + 8u * ROWB + 16u);
            }
#pragma unroll
            for (int sb = 0; sb < 3; ++sb) {
                uint32_t B[16][2];
#pragma unroll
                for (int nt = 0; nt < 16; ++nt) {
                    unsigned a = Bb + (unsigned)sb * SPLIT_B
                               + (unsigned)(nt * 8) * ROWB + (unsigned)kk * 32u;
                    B[nt][0] = lds32(a);
                    B[nt][1] = lds32(a + 16u);
                }
                const int nsa = (sb == 0) ? 3 : (sb == 1) ? 2 : 1;
#pragma unroll
                for (int sa = 0; sa < 3; ++sa) {
                    if (sa < nsa) {
#pragma unroll
                        for (int nt = 0; nt < 16; ++nt)
                            mma16816(acc[nt], A[sa], B[nt]);
                    }
                }
            }
        }

        __syncthreads();       // all warps done reading buf[c&1]
        if (c + 2 < NCHUNK) {  // refill the buffer we just finished
            const char* gb = (const char*)g_bsplit + (size_t)(c + 2) * CHUNK_B;
            const unsigned dst = base + ((c & 1) ? OFF_B1 : OFF_B0);
            for (unsigned i = tid * 16u; i < CHUNK_B; i += THREADS * 16u)
                CP_ASYNC16(dst + i, gb + i);
            CP_COMMIT();
        }

        // ---- epilogue from registers (overlaps the async copy) ---------
        const int cbase = c * BN;
#pragma unroll
        for (int nt = 0; nt < 16; ++nt) {
            const int col = nt * 8 + qlane * 2;
            const int gci = cbase + col;
            const float e2a = en2s[gci],  e2b = en2s[gci + 1];
            const float eia = einvs[gci], eib = einvs[gci + 1];
            const float d00 = acc[nt][0], d01 = acc[nt][1];
            const float d10 = acc[nt][2], d11 = acc[nt][3];
            float t;
            t = fmaf(-2.f, d00, zn0) + e2a; if (t < mind0) { mind0 = t; mini0 = gci; }
            t = fmaf(-2.f, d01, zn0) + e2b; if (t < mind0) { mind0 = t; mini0 = gci + 1; }
            t = fmaf(-2.f, d10, zn1) + e2a; if (t < mind1) { mind1 = t; mini1 = gci; }
            t = fmaf(-2.f, d11, zn1) + e2b; if (t < mind1) { mind1 = t; mini1 = gci + 1; }
            __stcs(reinterpret_cast<float2*>(sim0 + gci), make_float2(d00 * zi0 * eia, d01 * zi0 * eib));
            __stcs(reinterpret_cast<float2*>(sim1 + gci), make_float2(d10 * zi1 * eia, d11 * zi1 * eib));
        }

        if (c + 1 < NCHUNK) {
            if (c + 2 < NCHUNK) CP_WAIT(1); else CP_WAIT(0);
            __syncthreads();   // buf[(c+1)&1] visible to all warps
        }
    }

    // ---- argmin reduce across the quad (lanes differ in bits 0..1) -----
#pragma unroll
    for (int off = 1; off <= 2; off <<= 1) {
        float od0 = __shfl_xor_sync(0xffffffffu, mind0, off);
        int   oi0 = __shfl_xor_sync(0xffffffffu, mini0, off);
        if (od0 < mind0 || (od0 == mind0 && oi0 < mini0)) { mind0 = od0; mini0 = oi0; }
        float od1 = __shfl_xor_sync(0xffffffffu, mind1, off);
        int   oi1 = __shfl_xor_sync(0xffffffffu, mini1, off);
        if (od1 < mind1 || (od1 == mind1 && oi1 < mini1)) { mind1 = od1; mini1 = oi1; }
    }
    if (qlane == 0) {
        winidx[r0] = mini0;
        winidx[r1] = mini1;
    }
    __syncthreads();

    // ---- final per-token outputs: e, z_q, loss (fp32 from global) ------
    if (tid < BM) {
        const int    ix  = winidx[tid];
        const size_t tok = (size_t)blockIdx.x * BM + tid;
        const float4* er = reinterpret_cast<const float4*>(cbk + (size_t)ix * D);
        const float4* zr = reinterpret_cast<const float4*>(z + tok * D);
        float4* zq = reinterpret_cast<float4*>(zq_out + tok * D);
        float s = 0.f;
#pragma unroll
        for (int q = 0; q < 16; ++q) {
            float4 ev = er[q];
            float4 zv = zr[q];
            float dx = zv.x - ev.x, dy = zv.y - ev.y, dz = zv.z - ev.z, dw = zv.w - ev.w;
            s += dx * dx + dy * dy + dz * dz + dw * dw;
            zq[q] = ev;
        }
        loss_out[tok] = 1.25f * sqrtf(s);
        e_out[tok]    = (float)ix;
    }
}

extern "C" void kernel_launch(void* const* d_in, const int* in_sizes, int n_in,
                              void* d_out, int out_size) {
    const float* z   = (const float*)d_in[0];
    const float* cbk = (const float*)d_in[1];
    const int NT = in_sizes[0] / D;    // 131072

    float* out      = (float*)d_out;
    float* e_out    = out;
    float* zq_out   = e_out + NT;
    float* sim_out  = zq_out + (size_t)NT * D;
    float* loss_out = sim_out + (size_t)NT * KTOT;

    vq_prep_norm<<<(KTOT + 255) / 256, 256>>>(cbk);
    vq_prep_split<<<(KTOT * D + 255) / 256, 256>>>(cbk);

    cudaFuncSetAttribute(vq_mma_kernel, cudaFuncAttributeMaxDynamicSharedMemorySize, SMEM_REQ);
    vq_mma_kernel<<<NT / BM, THREADS, SMEM_REQ>>>(z, cbk, e_out, zq_out, sim_out, loss_out);
}